// round 14
// baseline (speedup 1.0000x reference)
#include <cuda_runtime.h>
#include <cstdint>

typedef unsigned long long ULL;

__device__ __forceinline__ ULL pack2(float lo, float hi) {
    ULL r; asm("mov.b64 %0, {%1, %2};" : "=l"(r) : "f"(lo), "f"(hi)); return r;
}
__device__ __forceinline__ void unpack2(ULL v, float& lo, float& hi) {
    asm("mov.b64 {%0, %1}, %2;" : "=f"(lo), "=f"(hi) : "l"(v));
}
__device__ __forceinline__ ULL fma2(ULL a, ULL b, ULL c) {
    ULL d; asm("fma.rn.f32x2 %0, %1, %2, %3;" : "=l"(d) : "l"(a), "l"(b), "l"(c)); return d;
}
__device__ __forceinline__ ULL add2(ULL a, ULL b) {
    ULL d; asm("add.rn.f32x2 %0, %1, %2;" : "=l"(d) : "l"(a), "l"(b)); return d;
}

// Hs partial slices: g_Hs[ir][node][h], ir = i-range (16 slices of 16 i's)
__device__ float g_Hs[16 * 1024 * 64];

// ============================================================================
// K1 v2b (j-coalesced, 2x blocks): grid 1024 = b(4) x jt(16) x ir(16); 128 thr.
// Block covers j in [jt*16,+16), i in [ir*16,+16). Contiguous 512B e loads.
// Thread = (jg in 4, hp in 32): 4 j's x h-pair {hp, hp+32}; i summed in-thread,
// zero cross-thread reduction. Partial -> g_Hs[ir].
// ============================================================================
__global__ __launch_bounds__(128, 8)
void k_edge(const float* __restrict__ edge,
            const float* __restrict__ W1,
            const float* __restrict__ b1) {
    __shared__ float es[2][8 * 16 * 16];   // [i_loc][j_loc][16 dup floats], 8KB each
    __shared__ float w1s[512];

    const int t  = threadIdx.x;
    const int bx = blockIdx.x;
    const int ir = bx & 15;
    const int jt = (bx >> 4) & 15;
    const int b  = bx >> 8;

    reinterpret_cast<float4*>(w1s)[t] = reinterpret_cast<const float4*>(W1)[t];

    const int jg = t >> 5;     // 4 j's: jt*16 + jg*4 + {0..3}  (uniform per warp)
    const int hp = t & 31;     // h-pair {hp, hp+32}

    // loader mapping: 256 float4 per 8-i stage, 2 per thread
    const int idx0 = t, idx1 = t + 128;
    const int i0 = idx0 >> 5, j0 = (idx0 >> 1) & 15, q0 = idx0 & 1;
    const int i1 = idx1 >> 5, j1 = (idx1 >> 1) & 15, q1 = idx1 & 1;
    const int jb = jt * 16;
    const int ib = ir * 16;
    const float4* srcA = reinterpret_cast<const float4*>(edge)
        + ((ULL)(b * 256 + ib + i0) * 256 + jb + j0) * 2 + q0;
    const float4* srcB = reinterpret_cast<const float4*>(edge)
        + ((ULL)(b * 256 + ib + i1) * 256 + jb + j1) * 2 + q1;
    const int dA = (i0 * 16 + j0) * 16 + q0 * 8;
    const int dB = (i1 * 16 + j1) * 16 + q1 * 8;

    // stage 0
    float4 vA = srcA[0];
    float4 vB = srcB[0];
    {
        float* p = &es[0][dA];
        *(float4*)&p[0] = make_float4(vA.x, vA.x, vA.y, vA.y);
        *(float4*)&p[4] = make_float4(vA.z, vA.z, vA.w, vA.w);
        p = &es[0][dB];
        *(float4*)&p[0] = make_float4(vB.x, vB.x, vB.y, vB.y);
        *(float4*)&p[4] = make_float4(vB.z, vB.z, vB.w, vB.w);
    }
    // prefetch stage 1 (8 i's ahead = +4096 float4)
    float4 nA = srcA[4096];
    float4 nB = srcB[4096];
    __syncthreads();

    ULL w12[8];
    const ULL b2i = pack2(b1[hp], b1[hp + 32]);
    #pragma unroll
    for (int f = 0; f < 8; f++)
        w12[f] = pack2(w1s[f * 64 + hp], w1s[f * 64 + hp + 32]);

    const ULL HMASK = 0x7FFFFFFF7FFFFFFFULL;
    ULL acc[4];
    #pragma unroll
    for (int jl = 0; jl < 4; jl++) acc[jl] = pack2(0.f, 0.f);

    #pragma unroll 1
    for (int s = 0; s < 2; s++) {
        const float* ebuf = es[s];
        #pragma unroll 2
        for (int il = 0; il < 8; il++) {
            #pragma unroll
            for (int jl = 0; jl < 4; jl++) {
                const float* row = &ebuf[(il * 16 + jg * 4 + jl) * 16];
                ulonglong2 p01 = *(const ulonglong2*)&row[0];
                ulonglong2 p23 = *(const ulonglong2*)&row[4];
                ulonglong2 p45 = *(const ulonglong2*)&row[8];
                ulonglong2 p67 = *(const ulonglong2*)&row[12];

                ULL h = fma2(p01.x, w12[0], b2i);
                h = fma2(p01.y, w12[1], h);
                h = fma2(p23.x, w12[2], h);
                h = fma2(p23.y, w12[3], h);
                h = fma2(p45.x, w12[4], h);
                h = fma2(p45.y, w12[5], h);
                h = fma2(p67.x, w12[6], h);
                h = fma2(p67.y, w12[7], h);

                ULL m = h & HMASK;            // |h| (alu pipe)
                acc[jl] = add2(acc[jl], add2(h, m));
            }
        }

        if (s == 0) {   // stage 1 into the other buffer
            float* p = &es[1][dA];
            *(float4*)&p[0] = make_float4(nA.x, nA.x, nA.y, nA.y);
            *(float4*)&p[4] = make_float4(nA.z, nA.z, nA.w, nA.w);
            p = &es[1][dB];
            *(float4*)&p[0] = make_float4(nB.x, nB.x, nB.y, nB.y);
            *(float4*)&p[4] = make_float4(nB.z, nB.z, nB.w, nB.w);
            __syncthreads();
        }
    }

    // per-thread store of slice partial (x0.5 folds the |h| ReLU)
    #pragma unroll
    for (int jl = 0; jl < 4; jl++) {
        const int node = b * 256 + jb + jg * 4 + jl;
        float lo, hi; unpack2(acc[jl], lo, hi);
        g_Hs[(ir * 1024 + node) * 64 + hp]      = lo * 0.5f;
        g_Hs[(ir * 1024 + node) * 64 + hp + 32] = hi * 0.5f;
    }
}

// ============================================================================
// K2 (R13 shape): grid 256 x 256 threads, 4 nodes/block; merges 16 slices.
// ============================================================================
__global__ __launch_bounds__(256, 2)
void k_node(const float* __restrict__ x,
            const float* __restrict__ W2,
            const float* __restrict__ b2,
            const float* __restrict__ root,
            float* __restrict__ out) {
    __shared__ ULL   hs2[4 * 64];
    __shared__ float wpart[4 * 256];
    __shared__ float wsf[4 * 256];
    __shared__ float rb[256];
    __shared__ float xs[64];

    const int t     = threadIdx.x;
    const int node0 = blockIdx.x * 4;
    const int cp    = t & 127;
    const int ph    = t >> 7;

    {   // merge 16 slices (fixed order -> deterministic)
        const int off = node0 * 64 + t;
        float s0 = 0.f, s1 = 0.f;
        #pragma unroll
        for (int k = 0; k < 8; k++) {
            s0 += g_Hs[off + (2 * k)     * 65536];
            s1 += g_Hs[off + (2 * k + 1) * 65536];
        }
        float hv = s0 + s1;
        hs2[t] = pack2(hv, hv);
    }
    rb[t] = 256.f * b2[t] + root[t];
    if (t < 64) xs[t] = x[node0 * 16 + t];

    ULL w2r[32];
    {
        const ULL* w2g = reinterpret_cast<const ULL*>(W2) + (ULL)(ph * 32) * 128 + cp;
        #pragma unroll
        for (int k = 0; k < 32; k++) w2r[k] = w2g[(ULL)k * 128];
    }
    __syncthreads();

    ULL acc[4];
    #pragma unroll
    for (int n = 0; n < 4; n++) acc[n] = pack2(0.f, 0.f);

    #pragma unroll
    for (int k = 0; k < 32; k++) {
        const ULL w = w2r[k];
        const int hh = ph * 32 + k;
        acc[0] = fma2(hs2[0 * 64 + hh], w, acc[0]);
        acc[1] = fma2(hs2[1 * 64 + hh], w, acc[1]);
        acc[2] = fma2(hs2[2 * 64 + hh], w, acc[2]);
        acc[3] = fma2(hs2[3 * 64 + hh], w, acc[3]);
    }

    if (ph == 0) {
        #pragma unroll
        for (int n = 0; n < 4; n++) {
            float lo, hi; unpack2(acc[n], lo, hi);
            wpart[n * 256 + 2 * cp]     = lo;
            wpart[n * 256 + 2 * cp + 1] = hi;
        }
    }
    __syncthreads();

    if (ph == 1) {
        #pragma unroll
        for (int n = 0; n < 4; n++) {
            float lo, hi; unpack2(acc[n], lo, hi);
            wsf[n * 256 + 2 * cp]     = lo + wpart[n * 256 + 2 * cp]     + rb[2 * cp];
            wsf[n * 256 + 2 * cp + 1] = hi + wpart[n * 256 + 2 * cp + 1] + rb[2 * cp + 1];
        }
    }
    __syncthreads();

    if (t < 64) {
        const int n = t >> 4, d = t & 15;
        float o = 0.f;
        #pragma unroll
        for (int c = 0; c < 16; c++)
            o += xs[n * 16 + c] * wsf[n * 256 + c * 16 + d];
        out[(node0 + n) * 16 + d] = o;
    }
}

extern "C" void kernel_launch(void* const* d_in, const int* in_sizes, int n_in,
                              void* d_out, int out_size) {
    const float* node_attr = (const float*)d_in[0];
    const float* edge_adj  = (const float*)d_in[1];
    const float* W1        = (const float*)d_in[2];
    const float* b1        = (const float*)d_in[3];
    const float* W2        = (const float*)d_in[4];
    const float* b2        = (const float*)d_in[5];
    const float* root      = (const float*)d_in[6];
    float* out = (float*)d_out;

    k_edge<<<1024, 128>>>(edge_adj, W1, b1);
    k_node<<<256, 256>>>(node_attr, W2, b2, root, out);
}

// round 15
// speedup vs baseline: 1.1366x; 1.1366x over previous
#include <cuda_runtime.h>
#include <cstdint>

typedef unsigned long long ULL;

__device__ __forceinline__ ULL pack2(float lo, float hi) {
    ULL r; asm("mov.b64 %0, {%1, %2};" : "=l"(r) : "f"(lo), "f"(hi)); return r;
}
__device__ __forceinline__ void unpack2(ULL v, float& lo, float& hi) {
    asm("mov.b64 {%0, %1}, %2;" : "=f"(lo), "=f"(hi) : "l"(v));
}
__device__ __forceinline__ ULL fma2(ULL a, ULL b, ULL c) {
    ULL d; asm("fma.rn.f32x2 %0, %1, %2, %3;" : "=l"(d) : "l"(a), "l"(b), "l"(c)); return d;
}

#define NN 256

// partial Hsum: slot [half][node][h]
__device__ float g_Hs[2 * 1024 * 64];

// swizzled row offset (floats): rows r and r+8 land in disjoint bank windows;
// offsets stay 16B-aligned for LDS.128 reads.
__device__ __forceinline__ int rowoff(int r) { return r * 20 + ((r >> 3) & 1) * 4; }

// ============================================================================
// K1 (identical to R8 best + PDL trigger): grid 2048 = (node, half).
// ============================================================================
__global__ __launch_bounds__(128, 6)
void k_edge(const float* __restrict__ edge,
            const float* __restrict__ W1,
            const float* __restrict__ b1) {
    // Allow the dependent kernel (k_node) to launch early; its
    // griddepcontrol.wait still orders its g_Hs reads after our completion.
    asm volatile("griddepcontrol.launch_dependents;");

    __shared__ float es[2][64 * 20 + 8];
    __shared__ float w1s[512];
    __shared__ float hsum[64];

    const int t    = threadIdx.x;
    const int bx   = blockIdx.x;
    const int node = bx >> 1;
    const int half = bx & 1;
    const int j    = node & 255;
    const int b    = node >> 8;

    if (t < 64) hsum[t] = 0.f;
    #pragma unroll
    for (int r = 0; r < 4; r++) w1s[t + 128 * r] = W1[t + 128 * r];

    const int ii = t >> 4;
    const int hp = t & 15;

    const int il = t >> 1, q = t & 1;
    const float4* src = reinterpret_cast<const float4*>(edge)
                        + ((ULL)(b * NN) * NN + j) * 2 + q
                        + (ULL)(half * 128) * 512;

    float4 v0 = src[(ULL)il * 512];
    {
        float* d = &es[0][rowoff(il) + q * 8];
        *(float2*)&d[0] = make_float2(v0.x, v0.x);
        *(float2*)&d[2] = make_float2(v0.y, v0.y);
        *(float2*)&d[4] = make_float2(v0.z, v0.z);
        *(float2*)&d[6] = make_float2(v0.w, v0.w);
    }
    float4 v1 = src[(ULL)(64 + il) * 512];
    __syncthreads();

    ULL w12[2][8], b2i[2];
    #pragma unroll
    for (int p = 0; p < 2; p++) {
        const int h0 = hp + p * 16;
        b2i[p] = pack2(b1[h0], b1[h0 + 32]);
        #pragma unroll
        for (int f = 0; f < 8; f++)
            w12[p][f] = pack2(w1s[f * 64 + h0], w1s[f * 64 + h0 + 32]);
    }

    const ULL HMASK = 0x7FFFFFFF7FFFFFFFULL;
    const ULL HALF2 = pack2(0.5f, 0.5f);
    ULL acc0 = pack2(0.f, 0.f), acc1 = acc0;

    #pragma unroll 1
    for (int c = 0; c < 2; c++) {
        const float* eb = es[c];
        #pragma unroll
        for (int s = 0; s < 8; s++) {
            const ULL* ep = (const ULL*)&eb[rowoff(ii * 8 + s)];
            ulonglong2 p01 = *(const ulonglong2*)&ep[0];
            ulonglong2 p23 = *(const ulonglong2*)&ep[2];
            ulonglong2 p45 = *(const ulonglong2*)&ep[4];
            ulonglong2 p67 = *(const ulonglong2*)&ep[6];
            ULL e0 = p01.x, e1 = p01.y, e2 = p23.x, e3 = p23.y;
            ULL e4 = p45.x, e5 = p45.y, e6 = p67.x, e7 = p67.y;

            ULL h0 = fma2(e0, w12[0][0], b2i[0]);
            ULL h1 = fma2(e0, w12[1][0], b2i[1]);
            h0 = fma2(e1, w12[0][1], h0);  h1 = fma2(e1, w12[1][1], h1);
            h0 = fma2(e2, w12[0][2], h0);  h1 = fma2(e2, w12[1][2], h1);
            h0 = fma2(e3, w12[0][3], h0);  h1 = fma2(e3, w12[1][3], h1);
            h0 = fma2(e4, w12[0][4], h0);  h1 = fma2(e4, w12[1][4], h1);
            h0 = fma2(e5, w12[0][5], h0);  h1 = fma2(e5, w12[1][5], h1);
            h0 = fma2(e6, w12[0][6], h0);  h1 = fma2(e6, w12[1][6], h1);
            h0 = fma2(e7, w12[0][7], h0);  h1 = fma2(e7, w12[1][7], h1);

            ULL a0 = h0 & HMASK;
            ULL a1 = h1 & HMASK;
            acc0 = fma2(h0, HALF2, acc0);
            acc0 = fma2(a0, HALF2, acc0);
            acc1 = fma2(h1, HALF2, acc1);
            acc1 = fma2(a1, HALF2, acc1);
        }

        if (c == 0) {
            float* d = &es[1][rowoff(il) + q * 8];
            *(float2*)&d[0] = make_float2(v1.x, v1.x);
            *(float2*)&d[2] = make_float2(v1.y, v1.y);
            *(float2*)&d[4] = make_float2(v1.z, v1.z);
            *(float2*)&d[6] = make_float2(v1.w, v1.w);
            __syncthreads();
        }
    }

    float a0, a1, a2, a3;
    unpack2(acc0, a0, a1);
    unpack2(acc1, a2, a3);
    a0 += __shfl_xor_sync(0xffffffffu, a0, 16);
    a1 += __shfl_xor_sync(0xffffffffu, a1, 16);
    a2 += __shfl_xor_sync(0xffffffffu, a2, 16);
    a3 += __shfl_xor_sync(0xffffffffu, a3, 16);
    if ((t & 16) == 0) {
        atomicAdd(&hsum[hp],      a0);
        atomicAdd(&hsum[hp + 32], a1);
        atomicAdd(&hsum[hp + 16], a2);
        atomicAdd(&hsum[hp + 48], a3);
    }
    __syncthreads();
    if (t < 64) g_Hs[(half * 1024 + node) * 64 + t] = hsum[t];
}

// ============================================================================
// K2 (identical to R8 best + PDL wait): grid 256 x 256 threads, 4 nodes/block.
// All g_Hs-independent staging happens BEFORE griddepcontrol.wait.
// ============================================================================
__global__ __launch_bounds__(256, 2)
void k_node(const float* __restrict__ x,
            const float* __restrict__ W2,
            const float* __restrict__ b2,
            const float* __restrict__ root,
            float* __restrict__ out) {
    __shared__ ULL   hs2[4 * 64];
    __shared__ float wpart[4 * 256];
    __shared__ float wsf[4 * 256];
    __shared__ float rb[256];
    __shared__ float xs[64];

    const int t     = threadIdx.x;
    const int node0 = blockIdx.x * 4;
    const int cp    = t & 127;
    const int ph    = t >> 7;

    // ---- g_Hs-independent preloads (overlap with k_edge tail) ----
    rb[t] = 256.f * b2[t] + root[t];
    if (t < 64) xs[t] = x[node0 * 16 + t];

    ULL w2r[32];
    {
        const ULL* w2g = reinterpret_cast<const ULL*>(W2) + (ULL)(ph * 32) * 128 + cp;
        #pragma unroll
        for (int k = 0; k < 32; k++) w2r[k] = w2g[(ULL)k * 128];
    }

    // ---- wait for k_edge grid completion (g_Hs visible) ----
    asm volatile("griddepcontrol.wait;" ::: "memory");

    {
        float hv = g_Hs[node0 * 64 + t] + g_Hs[1024 * 64 + node0 * 64 + t];
        hs2[t] = pack2(hv, hv);
    }
    __syncthreads();

    ULL acc[4];
    #pragma unroll
    for (int n = 0; n < 4; n++) acc[n] = pack2(0.f, 0.f);

    #pragma unroll
    for (int k = 0; k < 32; k++) {
        const ULL w = w2r[k];
        const int hh = ph * 32 + k;
        acc[0] = fma2(hs2[0 * 64 + hh], w, acc[0]);
        acc[1] = fma2(hs2[1 * 64 + hh], w, acc[1]);
        acc[2] = fma2(hs2[2 * 64 + hh], w, acc[2]);
        acc[3] = fma2(hs2[3 * 64 + hh], w, acc[3]);
    }

    if (ph == 0) {
        #pragma unroll
        for (int n = 0; n < 4; n++) {
            float lo, hi; unpack2(acc[n], lo, hi);
            wpart[n * 256 + 2 * cp]     = lo;
            wpart[n * 256 + 2 * cp + 1] = hi;
        }
    }
    __syncthreads();

    if (ph == 1) {
        #pragma unroll
        for (int n = 0; n < 4; n++) {
            float lo, hi; unpack2(acc[n], lo, hi);
            wsf[n * 256 + 2 * cp]     = lo + wpart[n * 256 + 2 * cp]     + rb[2 * cp];
            wsf[n * 256 + 2 * cp + 1] = hi + wpart[n * 256 + 2 * cp + 1] + rb[2 * cp + 1];
        }
    }
    __syncthreads();

    if (t < 64) {
        const int n = t >> 4, d = t & 15;
        float o = 0.f;
        #pragma unroll
        for (int c = 0; c < 16; c++)
            o += xs[n * 16 + c] * wsf[n * 256 + c * 16 + d];
        out[(node0 + n) * 16 + d] = o;
    }
}

extern "C" void kernel_launch(void* const* d_in, const int* in_sizes, int n_in,
                              void* d_out, int out_size) {
    const float* node_attr = (const float*)d_in[0];
    const float* edge_adj  = (const float*)d_in[1];
    const float* W1        = (const float*)d_in[2];
    const float* b1        = (const float*)d_in[3];
    const float* W2        = (const float*)d_in[4];
    const float* b2        = (const float*)d_in[5];
    const float* root      = (const float*)d_in[6];
    float* out = (float*)d_out;

    k_edge<<<2048, 128>>>(edge_adj, W1, b1);

    // k_node with programmatic dependent launch: overlaps its W2 preload with
    // k_edge's tail; griddepcontrol.wait provides the g_Hs ordering.
    cudaLaunchConfig_t cfg = {};
    cfg.gridDim  = dim3(256);
    cfg.blockDim = dim3(256);
    cfg.dynamicSmemBytes = 0;
    cfg.stream = 0;   // legacy default stream (same one the harness captures)
    cudaLaunchAttribute attrs[1];
    attrs[0].id = cudaLaunchAttributeProgrammaticStreamSerialization;
    attrs[0].val.programmaticStreamSerializationAllowed = 1;
    cfg.attrs = attrs;
    cfg.numAttrs = 1;
    cudaLaunchKernelEx(&cfg, k_node, node_attr, W2, b2, root, out);
}